// round 6
// baseline (speedup 1.0000x reference)
#include <cuda_runtime.h>
#include <math.h>

#define BB 4
#define NN 2048
#define CC 256
#define HH 16
#define DD 16

typedef unsigned long long u64;

// Scratch (allocation-free rule: __device__ globals)
__device__ float g_q[BB * HH * NN * DD];   // 8 MB
__device__ float g_k[BB * HH * NN * DD];   // 8 MB
__device__ float g_v[BB * HH * NN * DD];   // 8 MB
__device__ float g_o[BB * NN * CC];        // 8 MB (attention output, (B,N,C) layout)

// ---------------------------------------------------------------------------
// Packed f32x2 helpers (FFMA2 path — ptxas never emits these from C++)
// ---------------------------------------------------------------------------
__device__ __forceinline__ u64 pk2(float lo, float hi) {
    u64 r;
    asm("mov.b64 %0, {%1, %2};" : "=l"(r)
        : "r"(__float_as_uint(lo)), "r"(__float_as_uint(hi)));
    return r;
}
__device__ __forceinline__ void upk2(u64 v, float& lo, float& hi) {
    unsigned int a, b;
    asm("mov.b64 {%0, %1}, %2;" : "=r"(a), "=r"(b) : "l"(v));
    lo = __uint_as_float(a);
    hi = __uint_as_float(b);
}
__device__ __forceinline__ u64 ffma2(u64 a, u64 b, u64 c) {
    u64 d;
    asm("fma.rn.f32x2 %0, %1, %2, %3;" : "=l"(d) : "l"(a), "l"(b), "l"(c));
    return d;
}
__device__ __forceinline__ u64 fmul2(u64 a, u64 b) {
    u64 d;
    asm("mul.rn.f32x2 %0, %1, %2;" : "=l"(d) : "l"(a), "l"(b));
    return d;
}

// ---------------------------------------------------------------------------
// SGEMM 128x128 tile, 256 threads, 8x8 microtile, FFMA2 inner product.
// QKV variant scatters into g_q/g_k/g_v with (B,H,N,D) layout.
// ---------------------------------------------------------------------------
__global__ __launch_bounds__(256) void gemm_qkv_kernel(
    const float* __restrict__ A,
    const float* __restrict__ W,
    const float* __restrict__ bias) {
    const int K = CC;        // 256
    const int Nn = 3 * CC;   // 768
    __shared__ float As[16][128];
    __shared__ float Bs[16][128];
    int tid = threadIdx.x;
    int tx = tid & 15, ty = tid >> 4;
    int m0 = blockIdx.y * 128, n0 = blockIdx.x * 128;
    int arow = tid >> 1, acol = (tid & 1) << 3;   // A: 128 rows x 16 cols
    int brow = tid >> 4, bcol = (tid & 15) << 3;  // B: 16 rows x 128 cols

    u64 acc[8][4];
#pragma unroll
    for (int i = 0; i < 8; i++)
#pragma unroll
        for (int j = 0; j < 4; j++) acc[i][j] = 0ull;

    for (int k0 = 0; k0 < K; k0 += 16) {
        float4 a0 = *(const float4*)&A[(size_t)(m0 + arow) * K + k0 + acol];
        float4 a1 = *(const float4*)&A[(size_t)(m0 + arow) * K + k0 + acol + 4];
        As[acol + 0][arow] = a0.x; As[acol + 1][arow] = a0.y;
        As[acol + 2][arow] = a0.z; As[acol + 3][arow] = a0.w;
        As[acol + 4][arow] = a1.x; As[acol + 5][arow] = a1.y;
        As[acol + 6][arow] = a1.z; As[acol + 7][arow] = a1.w;
        *(float4*)&Bs[brow][bcol]     = *(const float4*)&W[(size_t)(k0 + brow) * Nn + n0 + bcol];
        *(float4*)&Bs[brow][bcol + 4] = *(const float4*)&W[(size_t)(k0 + brow) * Nn + n0 + bcol + 4];
        __syncthreads();
#pragma unroll 4
        for (int k = 0; k < 16; k++) {
            float ra[8];
            *(float4*)&ra[0] = *(const float4*)&As[k][ty * 8];
            *(float4*)&ra[4] = *(const float4*)&As[k][ty * 8 + 4];
            u64 rb[4];
            {
                ulonglong2 b0 = *(const ulonglong2*)&Bs[k][tx * 8];
                ulonglong2 b1 = *(const ulonglong2*)&Bs[k][tx * 8 + 4];
                rb[0] = b0.x; rb[1] = b0.y; rb[2] = b1.x; rb[3] = b1.y;
            }
#pragma unroll
            for (int i = 0; i < 8; i++) {
                u64 ad = pk2(ra[i], ra[i]);
#pragma unroll
                for (int j = 0; j < 4; j++) acc[i][j] = ffma2(ad, rb[j], acc[i][j]);
            }
        }
        __syncthreads();
    }
    // Scatter epilogue: col n in [0,768): t = n/256 selects q/k/v;
    // within: h = (n%256)/16, d = n%16.  row m: b = m/2048, nq = m%2048.
#pragma unroll
    for (int i = 0; i < 8; i++) {
        int m = m0 + ty * 8 + i;
        int b = m >> 11;
        int nq = m & 2047;
#pragma unroll
        for (int jp = 0; jp < 4; jp++) {
            float lo, hi;
            upk2(acc[i][jp], lo, hi);
#pragma unroll
            for (int e = 0; e < 2; e++) {
                int n = n0 + tx * 8 + jp * 2 + e;
                float val = (e ? hi : lo) + bias[n];
                int t = n >> 8;
                int rem = n & 255;
                int h = rem >> 4, d = rem & 15;
                float* dst = (t == 0) ? g_q : (t == 1) ? g_k : g_v;
                dst[((((size_t)b * HH + h) * NN + nq) << 4) + d] = val;
            }
        }
    }
}

__global__ __launch_bounds__(256) void gemm_proj_kernel(
    const float* __restrict__ W,
    const float* __restrict__ bias,
    float* __restrict__ out) {
    const int K = CC, Nn = CC;  // 256, 256
    const float* A = g_o;
    __shared__ float As[16][128];
    __shared__ float Bs[16][128];
    int tid = threadIdx.x;
    int tx = tid & 15, ty = tid >> 4;
    int m0 = blockIdx.y * 128, n0 = blockIdx.x * 128;
    int arow = tid >> 1, acol = (tid & 1) << 3;
    int brow = tid >> 4, bcol = (tid & 15) << 3;

    u64 acc[8][4];
#pragma unroll
    for (int i = 0; i < 8; i++)
#pragma unroll
        for (int j = 0; j < 4; j++) acc[i][j] = 0ull;

    for (int k0 = 0; k0 < K; k0 += 16) {
        float4 a0 = *(const float4*)&A[(size_t)(m0 + arow) * K + k0 + acol];
        float4 a1 = *(const float4*)&A[(size_t)(m0 + arow) * K + k0 + acol + 4];
        As[acol + 0][arow] = a0.x; As[acol + 1][arow] = a0.y;
        As[acol + 2][arow] = a0.z; As[acol + 3][arow] = a0.w;
        As[acol + 4][arow] = a1.x; As[acol + 5][arow] = a1.y;
        As[acol + 6][arow] = a1.z; As[acol + 7][arow] = a1.w;
        *(float4*)&Bs[brow][bcol]     = *(const float4*)&W[(size_t)(k0 + brow) * Nn + n0 + bcol];
        *(float4*)&Bs[brow][bcol + 4] = *(const float4*)&W[(size_t)(k0 + brow) * Nn + n0 + bcol + 4];
        __syncthreads();
#pragma unroll 4
        for (int k = 0; k < 16; k++) {
            float ra[8];
            *(float4*)&ra[0] = *(const float4*)&As[k][ty * 8];
            *(float4*)&ra[4] = *(const float4*)&As[k][ty * 8 + 4];
            u64 rb[4];
            {
                ulonglong2 b0 = *(const ulonglong2*)&Bs[k][tx * 8];
                ulonglong2 b1 = *(const ulonglong2*)&Bs[k][tx * 8 + 4];
                rb[0] = b0.x; rb[1] = b0.y; rb[2] = b1.x; rb[3] = b1.y;
            }
#pragma unroll
            for (int i = 0; i < 8; i++) {
                u64 ad = pk2(ra[i], ra[i]);
#pragma unroll
                for (int j = 0; j < 4; j++) acc[i][j] = ffma2(ad, rb[j], acc[i][j]);
            }
        }
        __syncthreads();
    }
#pragma unroll
    for (int i = 0; i < 8; i++) {
        int m = m0 + ty * 8 + i;
#pragma unroll
        for (int jp = 0; jp < 4; jp++) {
            float lo, hi;
            upk2(acc[i][jp], lo, hi);
            int n = n0 + tx * 8 + jp * 2;
            out[(size_t)m * Nn + n]     = lo + bias[n];
            out[(size_t)m * Nn + n + 1] = hi + bias[n + 1];
        }
    }
}

// ---------------------------------------------------------------------------
// Flash attention, no scaling. Each thread handles TWO query rows (D=16 in
// packed f32x2 regs). K/V tiles of 128 rows in smem, broadcast LDS. Online
// softmax with branched rescale. Inner loop: 32 FFMA2 per key for 2 queries.
// grid: (N/256, B*H), block: 128
// ---------------------------------------------------------------------------
__global__ __launch_bounds__(128) void attn_kernel() {
    constexpr int KT = 128;
    __shared__ u64 sK[KT * 8];
    __shared__ u64 sV[KT * 8];
    int bh = blockIdx.y;
    int q0 = blockIdx.x * 256;
    int tid = threadIdx.x;
    const float* Qb = g_q + (size_t)bh * NN * DD;
    const float* Kb = g_k + (size_t)bh * NN * DD;
    const float* Vb = g_v + (size_t)bh * NN * DD;

    u64 qA[8], qB[8];
    {
        const ulonglong2* qr = (const ulonglong2*)(Qb + (size_t)(q0 + tid) * DD);
#pragma unroll
        for (int i = 0; i < 4; i++) { ulonglong2 t = qr[i]; qA[2 * i] = t.x; qA[2 * i + 1] = t.y; }
        const ulonglong2* qs = (const ulonglong2*)(Qb + (size_t)(q0 + 128 + tid) * DD);
#pragma unroll
        for (int i = 0; i < 4; i++) { ulonglong2 t = qs[i]; qB[2 * i] = t.x; qB[2 * i + 1] = t.y; }
    }
    float mA = -INFINITY, lA = 0.f;
    float mB = -INFINITY, lB = 0.f;
    u64 accA[8], accB[8];
#pragma unroll
    for (int j = 0; j < 8; j++) { accA[j] = 0ull; accB[j] = 0ull; }

    for (int k0 = 0; k0 < NN; k0 += KT) {
        __syncthreads();
        const ulonglong2* Kg = (const ulonglong2*)(Kb + (size_t)k0 * DD);
        const ulonglong2* Vg = (const ulonglong2*)(Vb + (size_t)k0 * DD);
        ulonglong2* sK2 = (ulonglong2*)sK;
        ulonglong2* sV2 = (ulonglong2*)sV;
#pragma unroll
        for (int i = 0; i < 4; i++) {
            sK2[tid + i * 128] = Kg[tid + i * 128];
            sV2[tid + i * 128] = Vg[tid + i * 128];
        }
        __syncthreads();
#pragma unroll 2
        for (int kk = 0; kk < KT; kk++) {
            u64 k2[8];
            {
                const ulonglong2* kp = (const ulonglong2*)(sK + kk * 8);
                ulonglong2 t0 = kp[0], t1 = kp[1], t2 = kp[2], t3 = kp[3];
                k2[0] = t0.x; k2[1] = t0.y; k2[2] = t1.x; k2[3] = t1.y;
                k2[4] = t2.x; k2[5] = t2.y; k2[6] = t3.x; k2[7] = t3.y;
            }
            u64 sA2 = fmul2(qA[0], k2[0]);
            u64 sB2 = fmul2(qB[0], k2[0]);
#pragma unroll
            for (int j = 1; j < 8; j++) {
                sA2 = ffma2(qA[j], k2[j], sA2);
                sB2 = ffma2(qB[j], k2[j], sB2);
            }
            float alo, ahi, blo, bhi;
            upk2(sA2, alo, ahi);
            upk2(sB2, blo, bhi);
            float sA = alo + ahi;
            float sB = blo + bhi;

            if (sA > mA) {
                float c = __expf(mA - sA);  // 0 on first key
                mA = sA; lA *= c;
                u64 c2 = pk2(c, c);
#pragma unroll
                for (int j = 0; j < 8; j++) accA[j] = fmul2(accA[j], c2);
            }
            if (sB > mB) {
                float c = __expf(mB - sB);
                mB = sB; lB *= c;
                u64 c2 = pk2(c, c);
#pragma unroll
                for (int j = 0; j < 8; j++) accB[j] = fmul2(accB[j], c2);
            }
            float eA = __expf(sA - mA); lA += eA;
            float eB = __expf(sB - mB); lB += eB;

            u64 v2[8];
            {
                const ulonglong2* vp = (const ulonglong2*)(sV + kk * 8);
                ulonglong2 t0 = vp[0], t1 = vp[1], t2 = vp[2], t3 = vp[3];
                v2[0] = t0.x; v2[1] = t0.y; v2[2] = t1.x; v2[3] = t1.y;
                v2[4] = t2.x; v2[5] = t2.y; v2[6] = t3.x; v2[7] = t3.y;
            }
            u64 eA2 = pk2(eA, eA);
            u64 eB2 = pk2(eB, eB);
#pragma unroll
            for (int j = 0; j < 8; j++) {
                accA[j] = ffma2(eA2, v2[j], accA[j]);
                accB[j] = ffma2(eB2, v2[j], accB[j]);
            }
        }
    }

    int b = bh / HH, h = bh % HH;
    {
        float inv = 1.0f / lA;
        u64 i2 = pk2(inv, inv);
#pragma unroll
        for (int j = 0; j < 8; j++) accA[j] = fmul2(accA[j], i2);
        ulonglong2* o2 = (ulonglong2*)(g_o + ((size_t)(b * NN + q0 + tid) * CC) + h * DD);
        o2[0] = make_ulonglong2(accA[0], accA[1]);
        o2[1] = make_ulonglong2(accA[2], accA[3]);
        o2[2] = make_ulonglong2(accA[4], accA[5]);
        o2[3] = make_ulonglong2(accA[6], accA[7]);
    }
    {
        float inv = 1.0f / lB;
        u64 i2 = pk2(inv, inv);
#pragma unroll
        for (int j = 0; j < 8; j++) accB[j] = fmul2(accB[j], i2);
        ulonglong2* o2 = (ulonglong2*)(g_o + ((size_t)(b * NN + q0 + 128 + tid) * CC) + h * DD);
        o2[0] = make_ulonglong2(accB[0], accB[1]);
        o2[1] = make_ulonglong2(accB[2], accB[3]);
        o2[2] = make_ulonglong2(accB[4], accB[5]);
        o2[3] = make_ulonglong2(accB[6], accB[7]);
    }
}

// ---------------------------------------------------------------------------
extern "C" void kernel_launch(void* const* d_in, const int* in_sizes, int n_in,
                              void* d_out, int out_size) {
    const float* x      = (const float*)d_in[0];
    const float* w_qkv  = (const float*)d_in[1];
    const float* b_qkv  = (const float*)d_in[2];
    const float* w_proj = (const float*)d_in[3];
    const float* b_proj = (const float*)d_in[4];
    float* out = (float*)d_out;

    dim3 g1(6, 64);                // 768/128, 8192/128
    gemm_qkv_kernel<<<g1, 256>>>(x, w_qkv, b_qkv);

    dim3 g2(NN / 256, BB * HH);    // (8, 64)
    attn_kernel<<<g2, 128>>>();

    dim3 g3(2, 64);                // 256/128, 8192/128
    gemm_proj_kernel<<<g3, 256>>>(w_proj, b_proj, out);
}

// round 15
// speedup vs baseline: 2.1555x; 2.1555x over previous
#include <cuda_runtime.h>
#include <cuda_bf16.h>
#include <math.h>
#include <stdint.h>

#define BB 4
#define NN 2048
#define CC 256
#define HH 16
#define DD 16

// ---------------------------------------------------------------------------
// Device scratch (allocation-free rule: __device__ globals)
// ---------------------------------------------------------------------------
// Q/K split-bf16: [bh][token][32]  (ushort: d 0-15 = hi, 16-31 = lo)
__device__ unsigned short g_qs[(size_t)BB * HH * NN * 32];
__device__ unsigned short g_ks[(size_t)BB * HH * NN * 32];
// V^T split-bf16: [bh][split(2)][d(16)][token]  (split 0 = hi, 1 = lo)
__device__ unsigned short g_vts[(size_t)BB * HH * 32 * NN];
// attention output, (B, N, C) fp32
__device__ float g_o[(size_t)BB * NN * CC];

// ---------------------------------------------------------------------------
// mma.sync m16n8k16 bf16 (baseline PTX — works at compute_103)
// D/C fp32. A row-major, B col-major.
// ---------------------------------------------------------------------------
__device__ __forceinline__ void mma16816(float* d, const unsigned* a, const unsigned* b) {
    asm volatile(
        "mma.sync.aligned.m16n8k16.row.col.f32.bf16.bf16.f32 "
        "{%0,%1,%2,%3}, {%4,%5,%6,%7}, {%8,%9}, {%0,%1,%2,%3};"
        : "+f"(d[0]), "+f"(d[1]), "+f"(d[2]), "+f"(d[3])
        : "r"(a[0]), "r"(a[1]), "r"(a[2]), "r"(a[3]), "r"(b[0]), "r"(b[1]));
}

// pack two floats to bf16x2 (lo half = e0), return residuals
__device__ __forceinline__ unsigned pk_bf(float e0, float e1, float& r0, float& r1) {
    unsigned h0 = (unsigned)__bfloat16_as_ushort(__float2bfloat16_rn(e0));
    unsigned h1 = (unsigned)__bfloat16_as_ushort(__float2bfloat16_rn(e1));
    r0 = e0 - __uint_as_float(h0 << 16);
    r1 = e1 - __uint_as_float(h1 << 16);
    return h0 | (h1 << 16);
}
__device__ __forceinline__ unsigned pk_bf2(float e0, float e1) {
    unsigned h0 = (unsigned)__bfloat16_as_ushort(__float2bfloat16_rn(e0));
    unsigned h1 = (unsigned)__bfloat16_as_ushort(__float2bfloat16_rn(e1));
    return h0 | (h1 << 16);
}

// ---------------------------------------------------------------------------
// QKV GEMM (R1 64x64 config) with split-bf16 scatter epilogue
// ---------------------------------------------------------------------------
__global__ void gemm_qkv_kernel(const float* __restrict__ A,
                                const float* __restrict__ W,
                                const float* __restrict__ bias) {
    const int K = CC, Nn = 3 * CC;
    __shared__ float As[16][64];
    __shared__ float Bs[16][64];
    int tid = threadIdx.x;
    int tx = tid & 15, ty = tid >> 4;
    int m0 = blockIdx.y * 64, n0 = blockIdx.x * 64;
    int ar = tid >> 2, ac = (tid & 3) << 2;
    int br = tid >> 4, bc = (tid & 15) << 2;
    float acc[4][4] = {};
    for (int k0 = 0; k0 < K; k0 += 16) {
        float4 a = *(const float4*)&A[(size_t)(m0 + ar) * K + k0 + ac];
        As[ac + 0][ar] = a.x; As[ac + 1][ar] = a.y;
        As[ac + 2][ar] = a.z; As[ac + 3][ar] = a.w;
        *(float4*)&Bs[br][bc] = *(const float4*)&W[(size_t)(k0 + br) * Nn + n0 + bc];
        __syncthreads();
#pragma unroll
        for (int k = 0; k < 16; k++) {
            float ra[4], rb[4];
            *(float4*)ra = *(const float4*)&As[k][ty * 4];
            *(float4*)rb = *(const float4*)&Bs[k][tx * 4];
#pragma unroll
            for (int i = 0; i < 4; i++)
#pragma unroll
                for (int j = 0; j < 4; j++)
                    acc[i][j] += ra[i] * rb[j];
        }
        __syncthreads();
    }
#pragma unroll
    for (int i = 0; i < 4; i++) {
        int m = m0 + ty * 4 + i;
        int b = m >> 11, nq = m & 2047;
#pragma unroll
        for (int j = 0; j < 4; j++) {
            int n = n0 + tx * 4 + j;
            float val = acc[i][j] + bias[n];
            int t = n >> 8, rem = n & 255;
            int h = rem >> 4, d = rem & 15;
            int bh = b * HH + h;
            unsigned hu = (unsigned)__bfloat16_as_ushort(__float2bfloat16_rn(val));
            float res = val - __uint_as_float(hu << 16);
            unsigned lu = (unsigned)__bfloat16_as_ushort(__float2bfloat16_rn(res));
            if (t == 0) {
                size_t base = ((size_t)bh * NN + nq) * 32 + d;
                g_qs[base] = (unsigned short)hu; g_qs[base + 16] = (unsigned short)lu;
            } else if (t == 1) {
                size_t base = ((size_t)bh * NN + nq) * 32 + d;
                g_ks[base] = (unsigned short)hu; g_ks[base + 16] = (unsigned short)lu;
            } else {
                size_t base = ((size_t)bh * 32 + d) * NN + nq;
                g_vts[base] = (unsigned short)hu;
                g_vts[base + (size_t)16 * NN] = (unsigned short)lu;
            }
        }
    }
}

// ---------------------------------------------------------------------------
// Proj GEMM (R1 config, unchanged)
// ---------------------------------------------------------------------------
__global__ void gemm_proj_kernel(const float* __restrict__ W,
                                 const float* __restrict__ bias,
                                 float* __restrict__ out) {
    const int K = CC, Nn = CC;
    const float* A = g_o;
    __shared__ float As[16][64];
    __shared__ float Bs[16][64];
    int tid = threadIdx.x;
    int tx = tid & 15, ty = tid >> 4;
    int m0 = blockIdx.y * 64, n0 = blockIdx.x * 64;
    int ar = tid >> 2, ac = (tid & 3) << 2;
    int br = tid >> 4, bc = (tid & 15) << 2;
    float acc[4][4] = {};
    for (int k0 = 0; k0 < K; k0 += 16) {
        float4 a = *(const float4*)&A[(size_t)(m0 + ar) * K + k0 + ac];
        As[ac + 0][ar] = a.x; As[ac + 1][ar] = a.y;
        As[ac + 2][ar] = a.z; As[ac + 3][ar] = a.w;
        *(float4*)&Bs[br][bc] = *(const float4*)&W[(size_t)(k0 + br) * Nn + n0 + bc];
        __syncthreads();
#pragma unroll
        for (int k = 0; k < 16; k++) {
            float ra[4], rb[4];
            *(float4*)ra = *(const float4*)&As[k][ty * 4];
            *(float4*)rb = *(const float4*)&Bs[k][tx * 4];
#pragma unroll
            for (int i = 0; i < 4; i++)
#pragma unroll
                for (int j = 0; j < 4; j++)
                    acc[i][j] += ra[i] * rb[j];
        }
        __syncthreads();
    }
#pragma unroll
    for (int i = 0; i < 4; i++) {
        int m = m0 + ty * 4 + i;
#pragma unroll
        for (int j = 0; j < 4; j++) {
            int n = n0 + tx * 4 + j;
            out[(size_t)m * Nn + n] = acc[i][j] + bias[n];
        }
    }
}

// ---------------------------------------------------------------------------
// HMMA flash attention (no softmax scaling, no max subtraction).
// CTA = 128 threads = 4 warps; warp w owns 32 queries (2 m16 tiles).
// Per 128-key iter: S = QhKh^T + QhKl^T + QlKh^T via mma.m16n8k16;
// P = exp(S) split bf16 hi/lo in regs (S d-frag pair == PV a-frag);
// O += PhVh + PhVl + PlVh.  l accumulated in fp32, divide at end.
// Smem: sQ/sK rows of 40 ushorts (pad: conflict-free frag loads),
//       sVt rows of 136 ushorts.
// ---------------------------------------------------------------------------
#define QROW 40
#define VROW 136

__global__ __launch_bounds__(128) void attn_hmma_kernel() {
    __shared__ __align__(16) unsigned short sQ[128 * QROW];
    __shared__ __align__(16) unsigned short sK[128 * QROW];
    __shared__ __align__(16) unsigned short sVt[32 * VROW];

    int tid = threadIdx.x;
    int w = tid >> 5, lane = tid & 31;
    int g = lane >> 2, t = lane & 3;
    int bh = blockIdx.y, q0 = blockIdx.x * 128;

    // ---- load Q tile (128 rows x 32 ush) ----
    {
        const uint4* src = (const uint4*)(g_qs + ((size_t)bh * NN + q0 + tid) * 32);
        unsigned short* dq = sQ + tid * QROW;
#pragma unroll
        for (int u = 0; u < 4; u++) *(uint4*)(dq + u * 8) = src[u];
    }
    __syncthreads();

    // ---- Q fragments (resident) ----
    const unsigned* sQw = (const unsigned*)sQ;
    const unsigned* sKw = (const unsigned*)sK;
    const unsigned* sVw = (const unsigned*)sVt;
    unsigned qh[2][4], ql[2][4];
#pragma unroll
    for (int mt = 0; mt < 2; mt++) {
        int r0 = w * 32 + mt * 16 + g;
        int w0 = r0 * (QROW / 2), w8 = (r0 + 8) * (QROW / 2);
        qh[mt][0] = sQw[w0 + t];     qh[mt][1] = sQw[w8 + t];
        qh[mt][2] = sQw[w0 + t + 4]; qh[mt][3] = sQw[w8 + t + 4];
        ql[mt][0] = sQw[w0 + t + 8];  ql[mt][1] = sQw[w8 + t + 8];
        ql[mt][2] = sQw[w0 + t + 12]; ql[mt][3] = sQw[w8 + t + 12];
    }

    float o[2][2][4] = {};
    float l[4] = {};

    for (int j = 0; j < 16; j++) {
        int k0 = j * 128;
        __syncthreads();  // prior iter's smem reads complete (data in regs)
        // K tile
        {
            const uint4* src = (const uint4*)(g_ks + ((size_t)bh * NN + k0 + tid) * 32);
            unsigned short* dk = sK + tid * QROW;
#pragma unroll
            for (int u = 0; u < 4; u++) *(uint4*)(dk + u * 8) = src[u];
        }
        // V^T tiles (32 rows x 128 keys): each thread covers 32 keys = 4 uint4
        {
            int row = tid >> 2, part = tid & 3;
            const uint4* src = (const uint4*)(g_vts + ((size_t)bh * 32 + row) * NN + k0 + part * 32);
            unsigned short* dv = sVt + row * VROW + part * 32;
            *(uint4*)(dv + 0)  = src[0];
            *(uint4*)(dv + 8)  = src[1];
            *(uint4*)(dv + 16) = src[2];
            *(uint4*)(dv + 24) = src[3];
        }
        __syncthreads();

        for (int kc = 0; kc < 8; kc++) {
            // ---- K fragments (2 n-tiles of 8 keys) ----
            unsigned kh[2][2], kl[2][2];
#pragma unroll
            for (int nt = 0; nt < 2; nt++) {
                int wk = (kc * 16 + nt * 8 + g) * (QROW / 2);
                kh[nt][0] = sKw[wk + t];     kh[nt][1] = sKw[wk + t + 4];
                kl[nt][0] = sKw[wk + t + 8]; kl[nt][1] = sKw[wk + t + 12];
            }
            // ---- V fragments (2 d-tiles, hi/lo) ----
            unsigned vh[2][2], vl[2][2];
#pragma unroll
            for (int dt = 0; dt < 2; dt++) {
                int bhw = (dt * 8 + g) * (VROW / 2) + kc * 8 + t;
                int blw = (16 + dt * 8 + g) * (VROW / 2) + kc * 8 + t;
                vh[dt][0] = sVw[bhw]; vh[dt][1] = sVw[bhw + 4];
                vl[dt][0] = sVw[blw]; vl[dt][1] = sVw[blw + 4];
            }
#pragma unroll
            for (int mt = 0; mt < 2; mt++) {
                // ---- S = QhKh + QhKl + QlKh ----
                float s0[4] = {}, s1[4] = {};
                mma16816(s0, qh[mt], kh[0]);
                mma16816(s0, qh[mt], kl[0]);
                mma16816(s0, ql[mt], kh[0]);
                mma16816(s1, qh[mt], kh[1]);
                mma16816(s1, qh[mt], kl[1]);
                mma16816(s1, ql[mt], kh[1]);
                // ---- P = exp(S), split hi/lo, repack as A-frag ----
                float e00 = __expf(s0[0]), e01 = __expf(s0[1]);
                float e02 = __expf(s0[2]), e03 = __expf(s0[3]);
                float e10 = __expf(s1[0]), e11 = __expf(s1[1]);
                float e12 = __expf(s1[2]), e13 = __expf(s1[3]);
                l[2 * mt + 0] += e00 + e01 + e10 + e11;
                l[2 * mt + 1] += e02 + e03 + e12 + e13;
                unsigned ph[4], pl[4];
                float r0, r1;
                ph[0] = pk_bf(e00, e01, r0, r1); pl[0] = pk_bf2(r0, r1);
                ph[1] = pk_bf(e02, e03, r0, r1); pl[1] = pk_bf2(r0, r1);
                ph[2] = pk_bf(e10, e11, r0, r1); pl[2] = pk_bf2(r0, r1);
                ph[3] = pk_bf(e12, e13, r0, r1); pl[3] = pk_bf2(r0, r1);
                // ---- O += PhVh + PhVl + PlVh ----
#pragma unroll
                for (int dt = 0; dt < 2; dt++) {
                    mma16816(o[mt][dt], ph, vh[dt]);
                    mma16816(o[mt][dt], ph, vl[dt]);
                    mma16816(o[mt][dt], pl, vh[dt]);
                }
            }
        }
    }

    // ---- reduce l across the 4 t-lanes (cols) ----
#pragma unroll
    for (int i = 0; i < 4; i++) {
        l[i] += __shfl_xor_sync(0xFFFFFFFFu, l[i], 1);
        l[i] += __shfl_xor_sync(0xFFFFFFFFu, l[i], 2);
    }

    // ---- epilogue: O/l -> g_o (B, N, C) ----
    int b = bh >> 4, h = bh & 15;
#pragma unroll
    for (int mt = 0; mt < 2; mt++) {
        float inv0 = 1.0f / l[2 * mt + 0];
        float inv1 = 1.0f / l[2 * mt + 1];
        int row0 = q0 + w * 32 + mt * 16 + g;
#pragma unroll
        for (int dt = 0; dt < 2; dt++) {
            int col = h * 16 + dt * 8 + 2 * t;
            float2 v0 = make_float2(o[mt][dt][0] * inv0, o[mt][dt][1] * inv0);
            float2 v1 = make_float2(o[mt][dt][2] * inv1, o[mt][dt][3] * inv1);
            *(float2*)&g_o[((size_t)(b * NN) + row0) * CC + col] = v0;
            *(float2*)&g_o[((size_t)(b * NN) + row0 + 8) * CC + col] = v1;
        }
    }
}

// ---------------------------------------------------------------------------
extern "C" void kernel_launch(void* const* d_in, const int* in_sizes, int n_in,
                              void* d_out, int out_size) {
    const float* x      = (const float*)d_in[0];
    const float* w_qkv  = (const float*)d_in[1];
    const float* b_qkv  = (const float*)d_in[2];
    const float* w_proj = (const float*)d_in[3];
    const float* b_proj = (const float*)d_in[4];
    float* out = (float*)d_out;

    dim3 g1(12, 128);              // 768/64, 8192/64
    gemm_qkv_kernel<<<g1, 256>>>(x, w_qkv, b_qkv);

    dim3 g2(NN / 128, BB * HH);    // (16, 64)
    attn_hmma_kernel<<<g2, 128>>>();

    dim3 g3(4, 128);               // 256/64, 8192/64
    gemm_proj_kernel<<<g3, 256>>>(w_proj, b_proj, out);
}

// round 16
// speedup vs baseline: 2.7818x; 1.2906x over previous
#include <cuda_runtime.h>
#include <cuda_bf16.h>
#include <math.h>
#include <stdint.h>

#define BB 4
#define NN 2048
#define CC 256
#define HH 16
#define DD 16
#define LOG2E 1.4426950408889634f

// ---------------------------------------------------------------------------
// Device scratch (allocation-free rule: __device__ globals)
// ---------------------------------------------------------------------------
// x split planes: [m=8192][k=256]
__device__ unsigned short g_xh[(size_t)BB * NN * CC];
__device__ unsigned short g_xl[(size_t)BB * NN * CC];
// w_qkv transposed split planes: [n=768][k=256]
__device__ unsigned short g_wh[(size_t)3 * CC * CC];
__device__ unsigned short g_wl[(size_t)3 * CC * CC];
// Q/K split-bf16: [bh][token][32]  (ushort: d 0-15 = hi, 16-31 = lo). Q pre-scaled by log2e.
__device__ unsigned short g_qs[(size_t)BB * HH * NN * 32];
__device__ unsigned short g_ks[(size_t)BB * HH * NN * 32];
// V^T split-bf16: [bh][split(2)][d(16)][token]
__device__ unsigned short g_vts[(size_t)BB * HH * 32 * NN];
// attention output, (B, N, C) fp32
__device__ float g_o[(size_t)BB * NN * CC];

// ---------------------------------------------------------------------------
// Helpers
// ---------------------------------------------------------------------------
__device__ __forceinline__ void mma16816(float* d, const unsigned* a, const unsigned* b) {
    asm volatile(
        "mma.sync.aligned.m16n8k16.row.col.f32.bf16.bf16.f32 "
        "{%0,%1,%2,%3}, {%4,%5,%6,%7}, {%8,%9}, {%0,%1,%2,%3};"
        : "+f"(d[0]), "+f"(d[1]), "+f"(d[2]), "+f"(d[3])
        : "r"(a[0]), "r"(a[1]), "r"(a[2]), "r"(a[3]), "r"(b[0]), "r"(b[1]));
}
// pack pair to bf16x2, lo half = e0
__device__ __forceinline__ unsigned pk2cvt(float e0, float e1) {
    unsigned r;
    asm("cvt.rn.bf16x2.f32 %0, %1, %2;" : "=r"(r) : "f"(e1), "f"(e0));
    return r;
}
__device__ __forceinline__ float lo_bf(unsigned p) { return __uint_as_float(p << 16); }
__device__ __forceinline__ float hi_bf(unsigned p) { return __uint_as_float(p & 0xFFFF0000u); }
__device__ __forceinline__ float ex2f(float x) {
    float r;
    asm("ex2.approx.f32 %0, %1;" : "=f"(r) : "f"(x));
    return r;
}

// ---------------------------------------------------------------------------
// Conversion kernels: fp32 -> split bf16 hi/lo
// ---------------------------------------------------------------------------
__global__ void convert_x_kernel(const float* __restrict__ x) {
    int i = blockIdx.x * 256 + threadIdx.x;   // 2M elements
    float v = x[i];
    unsigned hu = (unsigned)__bfloat16_as_ushort(__float2bfloat16_rn(v));
    float res = v - __uint_as_float(hu << 16);
    unsigned lu = (unsigned)__bfloat16_as_ushort(__float2bfloat16_rn(res));
    g_xh[i] = (unsigned short)hu;
    g_xl[i] = (unsigned short)lu;
}
__global__ void convert_w_kernel(const float* __restrict__ w) {
    int idx = blockIdx.x * 256 + threadIdx.x;  // 196608 = 768*256
    int n = idx >> 8, k = idx & 255;
    float v = w[(size_t)k * (3 * CC) + n];
    unsigned hu = (unsigned)__bfloat16_as_ushort(__float2bfloat16_rn(v));
    float res = v - __uint_as_float(hu << 16);
    unsigned lu = (unsigned)__bfloat16_as_ushort(__float2bfloat16_rn(res));
    g_wh[idx] = (unsigned short)hu;
    g_wl[idx] = (unsigned short)lu;
}

// ---------------------------------------------------------------------------
// QKV GEMM via HMMA: tile M=128 x N=64, K=256 in 16 chunks. 128 threads.
// 3-term split: Ah*Bh + Ah*Bl + Al*Bh. Epilogue scatters split-bf16 q/k/v.
// sA rows pitch 40 ush: [16 hi | 16 lo | pad]. sB same for 64 n-rows.
// ---------------------------------------------------------------------------
__global__ __launch_bounds__(128) void gemm_qkv_hmma(const float* __restrict__ bias) {
    __shared__ __align__(16) unsigned short sA[128 * 40];
    __shared__ __align__(16) unsigned short sB[64 * 40];
    int tid = threadIdx.x;
    int w = tid >> 5, lane = tid & 31;
    int g = lane >> 2, t = lane & 3;
    int m0 = blockIdx.y * 128, n0 = blockIdx.x * 64;

    const unsigned* sAw = (const unsigned*)sA;
    const unsigned* sBw = (const unsigned*)sB;

    float acc[2][8][4] = {};

    for (int kc = 0; kc < 16; kc++) {
        int k0 = kc * 16;
        __syncthreads();
        // A: row = tid (128 rows), 16 hi + 16 lo
        {
            const uint4* xh = (const uint4*)(g_xh + (size_t)(m0 + tid) * CC + k0);
            const uint4* xl = (const uint4*)(g_xl + (size_t)(m0 + tid) * CC + k0);
            uint4* d = (uint4*)(sA + tid * 40);
            d[0] = xh[0]; d[1] = xh[1];
            *(uint4*)(sA + tid * 40 + 16) = xl[0];
            *(uint4*)(sA + tid * 40 + 24) = xl[1];
        }
        // B: 64 n-rows x (hi/lo): thread -> row = tid>>1, seg = tid&1
        {
            int brow = tid >> 1, bseg = tid & 1;
            const unsigned short* src = (bseg ? g_wl : g_wh) + (size_t)(n0 + brow) * CC + k0;
            *(uint4*)(sB + brow * 40 + bseg * 16)     = *(const uint4*)src;
            *(uint4*)(sB + brow * 40 + bseg * 16 + 8) = *(const uint4*)(src + 8);
        }
        __syncthreads();

        unsigned ah[2][4], al[2][4];
#pragma unroll
        for (int mt = 0; mt < 2; mt++) {
            int r0 = w * 32 + mt * 16 + g;
            int w0 = r0 * 20, w8 = (r0 + 8) * 20;
            ah[mt][0] = sAw[w0 + t];      ah[mt][1] = sAw[w8 + t];
            ah[mt][2] = sAw[w0 + t + 4];  ah[mt][3] = sAw[w8 + t + 4];
            al[mt][0] = sAw[w0 + t + 8];  al[mt][1] = sAw[w8 + t + 8];
            al[mt][2] = sAw[w0 + t + 12]; al[mt][3] = sAw[w8 + t + 12];
        }
#pragma unroll
        for (int nt = 0; nt < 8; nt++) {
            int wb = (nt * 8 + g) * 20;
            unsigned bh[2], bl[2];
            bh[0] = sBw[wb + t];     bh[1] = sBw[wb + t + 4];
            bl[0] = sBw[wb + t + 8]; bl[1] = sBw[wb + t + 12];
#pragma unroll
            for (int mt = 0; mt < 2; mt++) {
                mma16816(acc[mt][nt], ah[mt], bh);
                mma16816(acc[mt][nt], ah[mt], bl);
                mma16816(acc[mt][nt], al[mt], bh);
            }
        }
    }

    // Epilogue: scatter split-bf16 into g_qs/g_ks/g_vts (Q scaled by log2e)
#pragma unroll
    for (int mt = 0; mt < 2; mt++) {
#pragma unroll
        for (int rr = 0; rr < 2; rr++) {
            int m = m0 + w * 32 + mt * 16 + g + rr * 8;
            int b = m >> 11, nq = m & 2047;
#pragma unroll
            for (int nt = 0; nt < 8; nt++) {
#pragma unroll
                for (int e = 0; e < 2; e++) {
                    int n = n0 + nt * 8 + 2 * t + e;
                    float val = acc[mt][nt][rr * 2 + e] + bias[n];
                    int ty = n >> 8, rem = n & 255;
                    int h = rem >> 4, d = rem & 15;
                    int bh = b * HH + h;
                    if (ty == 0) val *= LOG2E;
                    unsigned hu = (unsigned)__bfloat16_as_ushort(__float2bfloat16_rn(val));
                    float res = val - __uint_as_float(hu << 16);
                    unsigned lu = (unsigned)__bfloat16_as_ushort(__float2bfloat16_rn(res));
                    if (ty == 0) {
                        size_t base = ((size_t)bh * NN + nq) * 32 + d;
                        g_qs[base] = (unsigned short)hu; g_qs[base + 16] = (unsigned short)lu;
                    } else if (ty == 1) {
                        size_t base = ((size_t)bh * NN + nq) * 32 + d;
                        g_ks[base] = (unsigned short)hu; g_ks[base + 16] = (unsigned short)lu;
                    } else {
                        size_t base = ((size_t)bh * 32 + d) * NN + nq;
                        g_vts[base] = (unsigned short)hu;
                        g_vts[base + (size_t)16 * NN] = (unsigned short)lu;
                    }
                }
            }
        }
    }
}

// ---------------------------------------------------------------------------
// Proj GEMM (scalar, unchanged)
// ---------------------------------------------------------------------------
__global__ void gemm_proj_kernel(const float* __restrict__ W,
                                 const float* __restrict__ bias,
                                 float* __restrict__ out) {
    const int K = CC, Nn = CC;
    const float* A = g_o;
    __shared__ float As[16][64];
    __shared__ float Bs[16][64];
    int tid = threadIdx.x;
    int tx = tid & 15, ty = tid >> 4;
    int m0 = blockIdx.y * 64, n0 = blockIdx.x * 64;
    int ar = tid >> 2, ac = (tid & 3) << 2;
    int br = tid >> 4, bc = (tid & 15) << 2;
    float acc[4][4] = {};
    for (int k0 = 0; k0 < K; k0 += 16) {
        float4 a = *(const float4*)&A[(size_t)(m0 + ar) * K + k0 + ac];
        As[ac + 0][ar] = a.x; As[ac + 1][ar] = a.y;
        As[ac + 2][ar] = a.z; As[ac + 3][ar] = a.w;
        *(float4*)&Bs[br][bc] = *(const float4*)&W[(size_t)(k0 + br) * Nn + n0 + bc];
        __syncthreads();
#pragma unroll
        for (int k = 0; k < 16; k++) {
            float ra[4], rb[4];
            *(float4*)ra = *(const float4*)&As[k][ty * 4];
            *(float4*)rb = *(const float4*)&Bs[k][tx * 4];
#pragma unroll
            for (int i = 0; i < 4; i++)
#pragma unroll
                for (int j = 0; j < 4; j++)
                    acc[i][j] += ra[i] * rb[j];
        }
        __syncthreads();
    }
#pragma unroll
    for (int i = 0; i < 4; i++) {
        int m = m0 + ty * 4 + i;
#pragma unroll
        for (int j = 0; j < 4; j++) {
            int n = n0 + tx * 4 + j;
            out[(size_t)m * Nn + n] = acc[i][j] + bias[n];
        }
    }
}

// ---------------------------------------------------------------------------
// HMMA flash attention (Q pre-scaled by log2e; p = ex2(s)).
// Same structure as R15-passing kernel; pack chain now uses cvt.rn.bf16x2.
// ---------------------------------------------------------------------------
#define QROW 40
#define VROW 136

__global__ __launch_bounds__(128) void attn_hmma_kernel() {
    __shared__ __align__(16) unsigned short sQ[128 * QROW];
    __shared__ __align__(16) unsigned short sK[128 * QROW];
    __shared__ __align__(16) unsigned short sVt[32 * VROW];

    int tid = threadIdx.x;
    int w = tid >> 5, lane = tid & 31;
    int g = lane >> 2, t = lane & 3;
    int bh = blockIdx.y, q0 = blockIdx.x * 128;

    {
        const uint4* src = (const uint4*)(g_qs + ((size_t)bh * NN + q0 + tid) * 32);
        unsigned short* dq = sQ + tid * QROW;
#pragma unroll
        for (int u = 0; u < 4; u++) *(uint4*)(dq + u * 8) = src[u];
    }
    __syncthreads();

    const unsigned* sQw = (const unsigned*)sQ;
    const unsigned* sKw = (const unsigned*)sK;
    const unsigned* sVw = (const unsigned*)sVt;
    unsigned qh[2][4], ql[2][4];
#pragma unroll
    for (int mt = 0; mt < 2; mt++) {
        int r0 = w * 32 + mt * 16 + g;
        int w0 = r0 * (QROW / 2), w8 = (r0 + 8) * (QROW / 2);
        qh[mt][0] = sQw[w0 + t];     qh[mt][1] = sQw[w8 + t];
        qh[mt][2] = sQw[w0 + t + 4]; qh[mt][3] = sQw[w8 + t + 4];
        ql[mt][0] = sQw[w0 + t + 8];  ql[mt][1] = sQw[w8 + t + 8];
        ql[mt][2] = sQw[w0 + t + 12]; ql[mt][3] = sQw[w8 + t + 12];
    }

    float o[2][2][4] = {};
    float l[4] = {};

    for (int j = 0; j < 16; j++) {
        int k0 = j * 128;
        __syncthreads();
        {
            const uint4* src = (const uint4*)(g_ks + ((size_t)bh * NN + k0 + tid) * 32);
            unsigned short* dk = sK + tid * QROW;
#pragma unroll
            for (int u = 0; u < 4; u++) *(uint4*)(dk + u * 8) = src[u];
        }
        {
            int row = tid >> 2, part = tid & 3;
            const uint4* src = (const uint4*)(g_vts + ((size_t)bh * 32 + row) * NN + k0 + part * 32);
            unsigned short* dv = sVt + row * VROW + part * 32;
            *(uint4*)(dv + 0)  = src[0];
            *(uint4*)(dv + 8)  = src[1];
            *(uint4*)(dv + 16) = src[2];
            *(uint4*)(dv + 24) = src[3];
        }
        __syncthreads();

        for (int kc = 0; kc < 8; kc++) {
            unsigned kh[2][2], kl[2][2];
#pragma unroll
            for (int nt = 0; nt < 2; nt++) {
                int wk = (kc * 16 + nt * 8 + g) * (QROW / 2);
                kh[nt][0] = sKw[wk + t];     kh[nt][1] = sKw[wk + t + 4];
                kl[nt][0] = sKw[wk + t + 8]; kl[nt][1] = sKw[wk + t + 12];
            }
            unsigned vh[2][2], vl[2][2];
#pragma unroll
            for (int dt = 0; dt < 2; dt++) {
                int bhw = (dt * 8 + g) * (VROW / 2) + kc * 8 + t;
                int blw = (16 + dt * 8 + g) * (VROW / 2) + kc * 8 + t;
                vh[dt][0] = sVw[bhw]; vh[dt][1] = sVw[bhw + 4];
                vl[dt][0] = sVw[blw]; vl[dt][1] = sVw[blw + 4];
            }
#pragma unroll
            for (int mt = 0; mt < 2; mt++) {
                float s0[4] = {}, s1[4] = {};
                mma16816(s0, qh[mt], kh[0]);
                mma16816(s0, qh[mt], kl[0]);
                mma16816(s0, ql[mt], kh[0]);
                mma16816(s1, qh[mt], kh[1]);
                mma16816(s1, qh[mt], kl[1]);
                mma16816(s1, ql[mt], kh[1]);
                float e00 = ex2f(s0[0]), e01 = ex2f(s0[1]);
                float e02 = ex2f(s0[2]), e03 = ex2f(s0[3]);
                float e10 = ex2f(s1[0]), e11 = ex2f(s1[1]);
                float e12 = ex2f(s1[2]), e13 = ex2f(s1[3]);
                l[2 * mt + 0] += e00 + e01 + e10 + e11;
                l[2 * mt + 1] += e02 + e03 + e12 + e13;
                unsigned ph[4], pl[4];
                ph[0] = pk2cvt(e00, e01);
                pl[0] = pk2cvt(e00 - lo_bf(ph[0]), e01 - hi_bf(ph[0]));
                ph[1] = pk2cvt(e02, e03);
                pl[1] = pk2cvt(e02 - lo_bf(ph[1]), e03 - hi_bf(ph[1]));
                ph[2] = pk2cvt(e10, e11);
                pl[2] = pk2cvt(e10 - lo_bf(ph[2]), e11 - hi_bf(ph[2]));
                ph[3] = pk2cvt(e12, e13);
                pl[3] = pk2cvt(e12 - lo_bf(ph[3]), e13 - hi_bf(ph[3]));
#pragma unroll
                for (int dt = 0; dt < 2; dt++) {
                    mma16816(o[mt][dt], ph, vh[dt]);
                    mma16816(o[mt][dt], ph, vl[dt]);
                    mma16816(o[mt][dt], pl, vh[dt]);
                }
            }
        }
    }

#pragma unroll
    for (int i = 0; i < 4; i++) {
        l[i] += __shfl_xor_sync(0xFFFFFFFFu, l[i], 1);
        l[i] += __shfl_xor_sync(0xFFFFFFFFu, l[i], 2);
    }

    int b = bh >> 4, h = bh & 15;
#pragma unroll
    for (int mt = 0; mt < 2; mt++) {
        float inv0 = 1.0f / l[2 * mt + 0];
        float inv1 = 1.0f / l[2 * mt + 1];
        int row0 = q0 + w * 32 + mt * 16 + g;
#pragma unroll
        for (int dt = 0; dt < 2; dt++) {
            int col = h * 16 + dt * 8 + 2 * t;
            float2 v0 = make_float2(o[mt][dt][0] * inv0, o[mt][dt][1] * inv0);
            float2 v1 = make_float2(o[mt][dt][2] * inv1, o[mt][dt][3] * inv1);
            *(float2*)&g_o[((size_t)(b * NN) + row0) * CC + col] = v0;
            *(float2*)&g_o[((size_t)(b * NN) + row0 + 8) * CC + col] = v1;
        }
    }
}

// ---------------------------------------------------------------------------
extern "C" void kernel_launch(void* const* d_in, const int* in_sizes, int n_in,
                              void* d_out, int out_size) {
    const float* x      = (const float*)d_in[0];
    const float* w_qkv  = (const float*)d_in[1];
    const float* b_qkv  = (const float*)d_in[2];
    const float* w_proj = (const float*)d_in[3];
    const float* b_proj = (const float*)d_in[4];
    float* out = (float*)d_out;

    convert_x_kernel<<<BB * NN * CC / 256, 256>>>(x);
    convert_w_kernel<<<3 * CC * CC / 256, 256>>>(w_qkv);

    dim3 g1(12, 64);               // 768/64 n-tiles, 8192/128 m-tiles
    gemm_qkv_hmma<<<g1, 128>>>(b_qkv);

    dim3 g2(NN / 128, BB * HH);    // (16, 64)
    attn_hmma_kernel<<<g2, 128>>>();

    dim3 g3(4, 128);               // 256/64, 8192/64
    gemm_proj_kernel<<<g3, 256>>>(w_proj, b_proj, out);
}